// round 2
// baseline (speedup 1.0000x reference)
#include <cuda_runtime.h>
#include <cuda_bf16.h>

#define D 256
#define MAXN 50000

// Scratch (allocation-free rule: __device__ globals). float4 => 16B alignment
// guaranteed for red.global.add.v4.f32 / vector loads.
__device__ float4 g_xs4[MAXN * D / 4];   // x scaled by dinv[row] (gather source)
__device__ float4 g_acc4[MAXN * D / 4];  // scatter target, init = xs (self loop)
__device__ float  g_deg[MAXN];
__device__ float  g_dinv[MAXN];
__device__ int    g_is64;                // 1 if edge_index is int64, else int32

// ---------------- edge dtype detection ----------------
// int64 indices < 50000 => every odd 32-bit word is 0. For random int32
// indices, OR of 1024 odd words is ~surely nonzero.
__global__ void k_detect(const int* __restrict__ w) {
    int acc = 0;
    for (int i = 1; i < 4096; i += 2) acc |= w[i];
    g_is64 = (acc == 0) ? 1 : 0;
}

__device__ __forceinline__ long long load_idx(const void* ei, long long pos, int is64) {
    if (is64) return ((const long long*)ei)[pos];
    return (long long)((const int*)ei)[pos];
}

// ---------------- degree / norm ----------------
__global__ void k_init_deg(int n) {
    int i = blockIdx.x * blockDim.x + threadIdx.x;
    if (i < n) g_deg[i] = 1.0f;  // self loop
}

__global__ void k_deg_scatter(const void* __restrict__ ei, int E, int n) {
    int e = blockIdx.x * blockDim.x + threadIdx.x;
    if (e >= E) return;
    int is64 = g_is64;
    long long dst = load_idx(ei, (long long)E + e, is64);
    if ((unsigned long long)dst < (unsigned long long)n)
        atomicAdd(&g_deg[dst], 1.0f);
}

__global__ void k_dinv(int n) {
    int i = blockIdx.x * blockDim.x + threadIdx.x;
    if (i < n) g_dinv[i] = rsqrtf(g_deg[i]);
}

// xs = x * dinv[row]; acc = xs  (float4 granularity: D/4 = 64 per row)
__global__ void k_scale_copy(const float* __restrict__ x, int n) {
    int t = blockIdx.x * blockDim.x + threadIdx.x;
    int total = n * (D / 4);
    if (t >= total) return;
    int row = t >> 6;
    float s = g_dinv[row];
    float4 v = reinterpret_cast<const float4*>(x)[t];
    v.x *= s; v.y *= s; v.z *= s; v.w *= s;
    g_xs4[t] = v;
    g_acc4[t] = v;
}

// ---------------- edge aggregation: acc[dst] += xs[src] ----------------
// One warp per edge. 256 floats = 64 float4 -> 2 float4 per lane.
__global__ void k_scatter_edges(const void* __restrict__ ei, int E, int n) {
    int warp = (blockIdx.x * blockDim.x + threadIdx.x) >> 5;
    int lane = threadIdx.x & 31;
    if (warp >= E) return;
    int is64 = g_is64;
    long long s = load_idx(ei, warp, is64);
    long long d = load_idx(ei, (long long)E + warp, is64);
    if ((unsigned long long)s >= (unsigned long long)n) return;
    if ((unsigned long long)d >= (unsigned long long)n) return;
    const float4* src = g_xs4 + s * (D / 4);
    float4* dst = g_acc4 + d * (D / 4);
#pragma unroll
    for (int i = 0; i < 2; i++) {
        int c = lane + 32 * i;
        float4 v = src[c];
        asm volatile(
            "red.global.add.v4.f32 [%0], {%1, %2, %3, %4};"
            :: "l"(dst + c), "f"(v.x), "f"(v.y), "f"(v.z), "f"(v.w)
            : "memory");
    }
}

// ---------------- fused dual GEMM + epilogue ----------------
// z[i][k] = dinv[i] * acc[i][k]   (folded into A load)
// out = relu(z@W1 + b1) + z@W2 + b2
#define BM 64
#define BN 64
#define BK 32
#define TM 4
#define TN 4

__global__ __launch_bounds__(256, 2)
void k_gemm_fused(const float* __restrict__ W1, const float* __restrict__ b1,
                  const float* __restrict__ W2, const float* __restrict__ b2,
                  float* __restrict__ out, int M) {
    __shared__ float As[BK][BM + 4];
    __shared__ float B1s[BK][BN];
    __shared__ float B2s[BK][BN];

    int tid = threadIdx.x;          // 0..255
    int tx = tid & 15;              // output col group
    int ty = tid >> 4;              // output row group
    int rowBase = blockIdx.x * BM;
    int colBase = blockIdx.y * BN;

    const float* acc_f = (const float*)g_acc4;

    float acc1[TM][TN] = {};
    float acc2[TM][TN] = {};

    for (int k0 = 0; k0 < D; k0 += BK) {
        // Load A tile (64 rows x 32 k), coalesced in k within a row.
#pragma unroll
        for (int i = 0; i < (BM * BK) / 256; i++) {
            int idx = tid + i * 256;
            int r = idx >> 5;       // /BK
            int kk = idx & 31;      // %BK
            int grow = rowBase + r;
            float v = 0.0f;
            if (grow < M) v = acc_f[grow * D + k0 + kk] * g_dinv[grow];
            As[kk][r] = v;
        }
        // Load B tiles (32 k x 64 cols), coalesced in col.
#pragma unroll
        for (int i = 0; i < (BK * BN) / 256; i++) {
            int idx = tid + i * 256;
            int kk = idx >> 6;      // /BN
            int c = idx & 63;       // %BN
            B1s[kk][c] = W1[(k0 + kk) * D + colBase + c];
            B2s[kk][c] = W2[(k0 + kk) * D + colBase + c];
        }
        __syncthreads();

#pragma unroll
        for (int k = 0; k < BK; k++) {
            float4 a  = *reinterpret_cast<const float4*>(&As[k][ty * TM]);
            float4 p  = *reinterpret_cast<const float4*>(&B1s[k][tx * TN]);
            float4 q  = *reinterpret_cast<const float4*>(&B2s[k][tx * TN]);
            float av[TM] = {a.x, a.y, a.z, a.w};
            float pv[TN] = {p.x, p.y, p.z, p.w};
            float qv[TN] = {q.x, q.y, q.z, q.w};
#pragma unroll
            for (int i = 0; i < TM; i++)
#pragma unroll
                for (int j = 0; j < TN; j++) {
                    acc1[i][j] = fmaf(av[i], pv[j], acc1[i][j]);
                    acc2[i][j] = fmaf(av[i], qv[j], acc2[i][j]);
                }
        }
        __syncthreads();
    }

#pragma unroll
    for (int i = 0; i < TM; i++) {
        int r = rowBase + ty * TM + i;
        if (r >= M) continue;
#pragma unroll
        for (int j = 0; j < TN; j++) {
            int c = colBase + tx * TN + j;
            float t1 = acc1[i][j] + b1[c];
            t1 = t1 > 0.0f ? t1 : 0.0f;
            out[r * D + c] = t1 + acc2[i][j] + b2[c];
        }
    }
}

// ---------------- launch ----------------
extern "C" void kernel_launch(void* const* d_in, const int* in_sizes, int n_in,
                              void* d_out, int out_size) {
    const float* x  = (const float*)d_in[0];
    const void*  ei = d_in[1];
    const float* W1 = (const float*)d_in[2];
    const float* b1 = (const float*)d_in[3];
    const float* W2 = (const float*)d_in[4];
    const float* b2 = (const float*)d_in[5];
    float* out      = (float*)d_out;

    int N = in_sizes[0] / D;   // 50000
    int E = in_sizes[1] / 2;   // 800000

    k_detect<<<1, 1>>>((const int*)ei);
    k_init_deg<<<(N + 255) / 256, 256>>>(N);
    k_deg_scatter<<<(E + 255) / 256, 256>>>(ei, E, N);
    k_dinv<<<(N + 255) / 256, 256>>>(N);
    k_scale_copy<<<(N * (D / 4) + 255) / 256, 256>>>(x, N);

    // one warp per edge
    long long totalThreads = (long long)E * 32;
    int blocks = (int)((totalThreads + 255) / 256);
    k_scatter_edges<<<blocks, 256>>>(ei, E, N);

    dim3 grid((N + BM - 1) / BM, D / BN);
    k_gemm_fused<<<grid, 256>>>(W1, b1, W2, b2, out, N);
}

// round 5
// speedup vs baseline: 1.5096x; 1.5096x over previous
#include <cuda_runtime.h>
#include <cuda_bf16.h>
#include <cstdint>

#define D 256
#define MAXN 50000
#define MP 50048            // M padded to multiple of 128
#define NB 512              // fused B rows (W1|W2 interleaved by n-tile)

// ---------------- scratch (__device__ globals; allocation-free rule) --------
__device__ float4 g_xs4[MAXN * D / 4];   // x scaled by dinv[row] (gather source)
__device__ float4 g_acc4[MAXN * D / 4];  // scatter target, init = xs (self loop)
__device__ float  g_deg[MAXN];
__device__ float  g_dinv[MAXN];
__device__ int    g_is64;
__device__ __nv_bfloat16 g_Ah[MP * D];   // z hi (z = dinv*acc), padded w/ zeros
__device__ __nv_bfloat16 g_Al[MP * D];   // z lo
__device__ __nv_bfloat16 g_Bh[NB * D];   // fused W hi  [n][k]
__device__ __nv_bfloat16 g_Bl[NB * D];   // fused W lo  [n][k]

// ---------------- edge dtype detection (parallel) ---------------------------
__global__ void k_detect(const int* __restrict__ w) {
    __shared__ int s[256];
    int acc = 0;
    for (int i = threadIdx.x * 2 + 1; i < 4096; i += 512) acc |= w[i];
    s[threadIdx.x] = acc;
    __syncthreads();
    for (int o = 128; o > 0; o >>= 1) {
        if (threadIdx.x < o) s[threadIdx.x] |= s[threadIdx.x + o];
        __syncthreads();
    }
    if (threadIdx.x == 0) g_is64 = (s[0] == 0) ? 1 : 0;
}

__device__ __forceinline__ long long load_idx(const void* ei, long long pos, int is64) {
    if (is64) return ((const long long*)ei)[pos];
    return (long long)((const int*)ei)[pos];
}

// ---------------- degree / norm ----------------
__global__ void k_init_deg(int n) {
    int i = blockIdx.x * blockDim.x + threadIdx.x;
    if (i < n) g_deg[i] = 1.0f;
}
__global__ void k_deg_scatter(const void* __restrict__ ei, int E, int n) {
    int e = blockIdx.x * blockDim.x + threadIdx.x;
    if (e >= E) return;
    long long dst = load_idx(ei, (long long)E + e, g_is64);
    if ((unsigned long long)dst < (unsigned long long)n)
        atomicAdd(&g_deg[dst], 1.0f);
}
__global__ void k_dinv(int n) {
    int i = blockIdx.x * blockDim.x + threadIdx.x;
    if (i < n) g_dinv[i] = rsqrtf(g_deg[i]);
}
__global__ void k_scale_copy(const float* __restrict__ x, int n) {
    int t = blockIdx.x * blockDim.x + threadIdx.x;
    int total = n * (D / 4);
    if (t >= total) return;
    int row = t >> 6;
    float s = g_dinv[row];
    float4 v = reinterpret_cast<const float4*>(x)[t];
    v.x *= s; v.y *= s; v.z *= s; v.w *= s;
    g_xs4[t] = v;
    g_acc4[t] = v;
}

// ---------------- edge aggregation: acc[dst] += xs[src] ---------------------
__global__ void k_scatter_edges(const void* __restrict__ ei, int E, int n) {
    int warp = (blockIdx.x * blockDim.x + threadIdx.x) >> 5;
    int lane = threadIdx.x & 31;
    if (warp >= E) return;
    int is64 = g_is64;
    long long s = load_idx(ei, warp, is64);
    long long d = load_idx(ei, (long long)E + warp, is64);
    if ((unsigned long long)s >= (unsigned long long)n) return;
    if ((unsigned long long)d >= (unsigned long long)n) return;
    const float4* src = g_xs4 + s * (D / 4);
    float4* dst = g_acc4 + d * (D / 4);
#pragma unroll
    for (int i = 0; i < 2; i++) {
        int c = lane + 32 * i;
        float4 v = src[c];
        asm volatile("red.global.add.v4.f32 [%0], {%1, %2, %3, %4};"
                     :: "l"(dst + c), "f"(v.x), "f"(v.y), "f"(v.z), "f"(v.w)
                     : "memory");
    }
}

// ---------------- A prep: z = dinv*acc, split into global bf16 hi/lo --------
__global__ void k_prep_A(int M) {
    int t = blockIdx.x * blockDim.x + threadIdx.x;   // one per 8 elements
    int total = MP * (D / 8);
    if (t >= total) return;
    int row = t >> 5;
    int kg = t & 31;
    union { __nv_bfloat16 h[8]; uint4 v; } ph, pl;
    if (row < M) {
        float s = g_dinv[row];
        float4 v0 = g_acc4[row * (D / 4) + kg * 2];
        float4 v1 = g_acc4[row * (D / 4) + kg * 2 + 1];
        float f[8] = {v0.x * s, v0.y * s, v0.z * s, v0.w * s,
                      v1.x * s, v1.y * s, v1.z * s, v1.w * s};
#pragma unroll
        for (int e = 0; e < 8; e++) {
            ph.h[e] = __float2bfloat16(f[e]);
            pl.h[e] = __float2bfloat16(f[e] - __bfloat162float(ph.h[e]));
        }
    } else {
        ph.v = make_uint4(0, 0, 0, 0);
        pl.v = ph.v;
    }
    reinterpret_cast<uint4*>(g_Ah)[t] = ph.v;
    reinterpret_cast<uint4*>(g_Al)[t] = pl.v;
}

// ---------------- B prep: interleaved [W1|W2] split into bf16 hi/lo ---------
// B row n = j*128 + l:  l<64 -> W1 col (j*64+l),  l>=64 -> W2 col (j*64+l-64)
__global__ void k_prep_B(const float* __restrict__ W1, const float* __restrict__ W2) {
    int n = blockIdx.x;       // 0..511
    int k = threadIdx.x;      // 0..255
    int j = n >> 7, l = n & 127;
    const float* W = (l < 64) ? W1 : W2;
    int col = j * 64 + (l & 63);
    float w = W[k * D + col];
    __nv_bfloat16 hi = __float2bfloat16(w);
    float lo = w - __bfloat162float(hi);
    g_Bh[n * D + k] = hi;
    g_Bl[n * D + k] = __float2bfloat16(lo);
}

// ---------------- mma.sync bf16 helper --------------------------------------
__device__ __forceinline__ void mma16816(float c[4], const uint32_t a[4],
                                         const uint32_t b[2]) {
    asm volatile(
        "mma.sync.aligned.m16n8k16.row.col.f32.bf16.bf16.f32 "
        "{%0,%1,%2,%3}, {%4,%5,%6,%7}, {%8,%9}, {%0,%1,%2,%3};"
        : "+f"(c[0]), "+f"(c[1]), "+f"(c[2]), "+f"(c[3])
        : "r"(a[0]), "r"(a[1]), "r"(a[2]), "r"(a[3]), "r"(b[0]), "r"(b[1]));
}

// ---------------- HMMA split-bf16 dual GEMM + fused epilogue ----------------
// Per CTA: rows [bx*128, +128), cols j*64..j*64+63 of BOTH W1 and W2.
// out[r][cb+c] = relu(D1 + b1[cb+c]) + D2 + b2[cb+c]
#define PITCH 40   // smem row pitch in bf16 elements (80B = 20 banks, 16B-aligned)

__global__ __launch_bounds__(256)
void k_gemm_mma(const float* __restrict__ b1, const float* __restrict__ b2,
                float* __restrict__ out, int M) {
    __shared__ uint16_t AsH[128 * PITCH];
    __shared__ uint16_t AsL[128 * PITCH];
    __shared__ uint16_t Bs[4][64 * PITCH];   // [0]=W1h [1]=W1l [2]=W2h [3]=W2l

    int tid = threadIdx.x;
    int wid = tid >> 5;
    int lane = tid & 31;
    int wm = wid >> 1;           // 0..3  (rows wm*32)
    int wn = wid & 1;            // 0..1  (cols wn*32)
    int g = lane >> 2;           // 0..7
    int tig = lane & 3;          // 0..3
    int rowBase = blockIdx.x * 128;
    int j = blockIdx.y;          // col tile 0..3
    int cb = j * 64;

    float acc1[2][4][4] = {};    // [mb][nb][4]
    float acc2[2][4][4] = {};

    const uint4* Ah4 = reinterpret_cast<const uint4*>(g_Ah);
    const uint4* Al4 = reinterpret_cast<const uint4*>(g_Al);
    const uint4* Bh4 = reinterpret_cast<const uint4*>(g_Bh);
    const uint4* Bl4 = reinterpret_cast<const uint4*>(g_Bl);

    for (int k0 = 0; k0 < D; k0 += 32) {
        // load A tile 128x32 (hi/lo): 512 uint4 each, 2 per thread
#pragma unroll
        for (int it = 0; it < 2; it++) {
            int idx = tid + it * 256;
            int r = idx >> 2;
            int kg = idx & 3;
            uint4 vh = Ah4[(size_t)(rowBase + r) * 32 + (k0 >> 3) + kg];
            uint4 vl = Al4[(size_t)(rowBase + r) * 32 + (k0 >> 3) + kg];
            *reinterpret_cast<uint4*>(&AsH[r * PITCH + kg * 8]) = vh;
            *reinterpret_cast<uint4*>(&AsL[r * PITCH + kg * 8]) = vl;
        }
        // load B tiles: 4 buffers x 64 rows x 32k = 256 uint4 each
        {
            int r = tid >> 2;
            int kg = tid & 3;
            int n1 = j * 128 + r;          // W1 rows
            int n2 = j * 128 + 64 + r;     // W2 rows
            uint4 w1h = Bh4[(size_t)n1 * 32 + (k0 >> 3) + kg];
            uint4 w1l = Bl4[(size_t)n1 * 32 + (k0 >> 3) + kg];
            uint4 w2h = Bh4[(size_t)n2 * 32 + (k0 >> 3) + kg];
            uint4 w2l = Bl4[(size_t)n2 * 32 + (k0 >> 3) + kg];
            *reinterpret_cast<uint4*>(&Bs[0][r * PITCH + kg * 8]) = w1h;
            *reinterpret_cast<uint4*>(&Bs[1][r * PITCH + kg * 8]) = w1l;
            *reinterpret_cast<uint4*>(&Bs[2][r * PITCH + kg * 8]) = w2h;
            *reinterpret_cast<uint4*>(&Bs[3][r * PITCH + kg * 8]) = w2l;
        }
        __syncthreads();

#pragma unroll
        for (int ks = 0; ks < 2; ks++) {
            int kb = ks * 16;
            // A fragments (hi and lo) for 2 m-blocks
            uint32_t ah[2][4], al[2][4];
#pragma unroll
            for (int mb = 0; mb < 2; mb++) {
                int r = wm * 32 + mb * 16 + g;
                const uint16_t* pH = &AsH[r * PITCH + kb + tig * 2];
                const uint16_t* pL = &AsL[r * PITCH + kb + tig * 2];
                ah[mb][0] = *(const uint32_t*)pH;
                ah[mb][1] = *(const uint32_t*)(pH + 8 * PITCH);
                ah[mb][2] = *(const uint32_t*)(pH + 8);
                ah[mb][3] = *(const uint32_t*)(pH + 8 * PITCH + 8);
                al[mb][0] = *(const uint32_t*)pL;
                al[mb][1] = *(const uint32_t*)(pL + 8 * PITCH);
                al[mb][2] = *(const uint32_t*)(pL + 8);
                al[mb][3] = *(const uint32_t*)(pL + 8 * PITCH + 8);
            }
            // B fragments
            uint32_t b1h[4][2], b1l[4][2], b2h[4][2], b2l[4][2];
#pragma unroll
            for (int nb = 0; nb < 4; nb++) {
                int n = wn * 32 + nb * 8 + g;
                int o = n * PITCH + kb + tig * 2;
                b1h[nb][0] = *(const uint32_t*)&Bs[0][o];
                b1h[nb][1] = *(const uint32_t*)&Bs[0][o + 8];
                b1l[nb][0] = *(const uint32_t*)&Bs[1][o];
                b1l[nb][1] = *(const uint32_t*)&Bs[1][o + 8];
                b2h[nb][0] = *(const uint32_t*)&Bs[2][o];
                b2h[nb][1] = *(const uint32_t*)&Bs[2][o + 8];
                b2l[nb][0] = *(const uint32_t*)&Bs[3][o];
                b2l[nb][1] = *(const uint32_t*)&Bs[3][o + 8];
            }
#pragma unroll
            for (int mb = 0; mb < 2; mb++)
#pragma unroll
                for (int nb = 0; nb < 4; nb++) {
                    mma16816(acc1[mb][nb], ah[mb], b1h[nb]);
                    mma16816(acc1[mb][nb], ah[mb], b1l[nb]);
                    mma16816(acc1[mb][nb], al[mb], b1h[nb]);
                    mma16816(acc2[mb][nb], ah[mb], b2h[nb]);
                    mma16816(acc2[mb][nb], ah[mb], b2l[nb]);
                    mma16816(acc2[mb][nb], al[mb], b2h[nb]);
                }
        }
        __syncthreads();
    }

    // ---- epilogue: out = relu(acc1 + b1) + acc2 + b2 ----
#pragma unroll
    for (int mb = 0; mb < 2; mb++) {
#pragma unroll
        for (int nb = 0; nb < 4; nb++) {
            int c = cb + wn * 32 + nb * 8 + tig * 2;
            float bb1a = __ldg(&b1[c]),     bb1b = __ldg(&b1[c + 1]);
            float bb2a = __ldg(&b2[c]),     bb2b = __ldg(&b2[c + 1]);
#pragma unroll
            for (int h = 0; h < 2; h++) {   // h=0 -> c0,c1 ; h=1 -> c2,c3
                int r = rowBase + wm * 32 + mb * 16 + g + h * 8;
                if (r >= M) continue;
                float z1 = acc1[mb][nb][h * 2]     + bb1a;
                float z2 = acc1[mb][nb][h * 2 + 1] + bb1b;
                z1 = z1 > 0.0f ? z1 : 0.0f;
                z2 = z2 > 0.0f ? z2 : 0.0f;
                float2 o;
                o.x = z1 + acc2[mb][nb][h * 2]     + bb2a;
                o.y = z2 + acc2[mb][nb][h * 2 + 1] + bb2b;
                *reinterpret_cast<float2*>(out + (size_t)r * D + c) = o;
            }
        }
    }
}

// ---------------- launch ----------------
extern "C" void kernel_launch(void* const* d_in, const int* in_sizes, int n_in,
                              void* d_out, int out_size) {
    const float* x  = (const float*)d_in[0];
    const void*  ei = d_in[1];
    const float* W1 = (const float*)d_in[2];
    const float* b1 = (const float*)d_in[3];
    const float* W2 = (const float*)d_in[4];
    const float* b2 = (const float*)d_in[5];
    float* out      = (float*)d_out;

    int N = in_sizes[0] / D;   // 50000
    int E = in_sizes[1] / 2;   // 800000

    k_detect<<<1, 256>>>((const int*)ei);
    k_init_deg<<<(N + 255) / 256, 256>>>(N);
    k_deg_scatter<<<(E + 255) / 256, 256>>>(ei, E, N);
    k_dinv<<<(N + 255) / 256, 256>>>(N);
    k_scale_copy<<<(N * (D / 4) + 255) / 256, 256>>>(x, N);

    long long totalThreads = (long long)E * 32;
    int blocks = (int)((totalThreads + 255) / 256);
    k_scatter_edges<<<blocks, 256>>>(ei, E, N);

    k_prep_A<<<(MP * (D / 8) + 255) / 256, 256>>>(N);
    k_prep_B<<<NB, 256>>>(W1, W2);

    dim3 grid(MP / 128, 4);
    k_gemm_mma<<<grid, 256>>>(b1, b2, out, N);
}

// round 6
// speedup vs baseline: 2.1033x; 1.3933x over previous
#include <cuda_runtime.h>
#include <cuda_bf16.h>
#include <cstdint>

#define D 256
#define MAXN 50000
#define MP 50048            // M padded to multiple of 128
#define NB 512              // fused B rows (W1|W2 interleaved by n-tile)
#define MAXE 800000
#define SCAN_B 256

// ---------------- scratch (__device__ globals; allocation-free rule) --------
__device__ float4 g_xs4[MAXN * D / 4];   // x scaled by dinv[row] (gather source)
__device__ float  g_dinv[MAXN];
__device__ int    g_hist[MAXN];
__device__ int    g_off[MAXN + 1];
__device__ int    g_cursor[MAXN];
__device__ int    g_csr[MAXE];
__device__ int    g_bsum[256];
__device__ int    g_bspine[256];
__device__ int    g_is64;
__device__ __nv_bfloat16 g_Ah[MP * D];   // z hi (z = dinv*agg), padded w/ zeros
__device__ __nv_bfloat16 g_Al[MP * D];   // z lo
__device__ __nv_bfloat16 g_Bh[NB * D];   // fused W hi  [n][k]
__device__ __nv_bfloat16 g_Bl[NB * D];   // fused W lo  [n][k]

// ---------------- edge dtype detection (parallel) ---------------------------
__global__ void k_detect(const int* __restrict__ w) {
    __shared__ int s[256];
    int acc = 0;
    for (int i = threadIdx.x * 2 + 1; i < 4096; i += 512) acc |= w[i];
    s[threadIdx.x] = acc;
    __syncthreads();
    for (int o = 128; o > 0; o >>= 1) {
        if (threadIdx.x < o) s[threadIdx.x] |= s[threadIdx.x + o];
        __syncthreads();
    }
    if (threadIdx.x == 0) g_is64 = (s[0] == 0) ? 1 : 0;
}

__device__ __forceinline__ long long load_idx(const void* ei, long long pos, int is64) {
    if (is64) return ((const long long*)ei)[pos];
    return (long long)((const int*)ei)[pos];
}

// ---------------- CSR build --------------------------------------------------
__global__ void k_zero_hist(int n) {
    int i = blockIdx.x * blockDim.x + threadIdx.x;
    if (i < n) g_hist[i] = 0;
}
__global__ void k_hist(const void* __restrict__ ei, int E, int n) {
    int e = blockIdx.x * blockDim.x + threadIdx.x;
    if (e >= E) return;
    long long dst = load_idx(ei, (long long)E + e, g_is64);
    if ((unsigned long long)dst < (unsigned long long)n)
        atomicAdd(&g_hist[dst], 1);
}
// per-block exclusive scan of hist -> off, block totals -> bsum
__global__ void k_scan_block(int n) {
    __shared__ int s[SCAN_B];
    int i = blockIdx.x * SCAN_B + threadIdx.x;
    int v = (i < n) ? g_hist[i] : 0;
    s[threadIdx.x] = v;
    __syncthreads();
#pragma unroll
    for (int o = 1; o < SCAN_B; o <<= 1) {
        int t = (threadIdx.x >= o) ? s[threadIdx.x - o] : 0;
        __syncthreads();
        s[threadIdx.x] += t;
        __syncthreads();
    }
    if (i < n) g_off[i] = s[threadIdx.x] - v;
    if (threadIdx.x == SCAN_B - 1) g_bsum[blockIdx.x] = s[threadIdx.x];
}
__global__ void k_scan_spine(int nb, int n) {
    __shared__ int s[SCAN_B];
    int v = (threadIdx.x < nb) ? g_bsum[threadIdx.x] : 0;
    s[threadIdx.x] = v;
    __syncthreads();
#pragma unroll
    for (int o = 1; o < SCAN_B; o <<= 1) {
        int t = (threadIdx.x >= o) ? s[threadIdx.x - o] : 0;
        __syncthreads();
        s[threadIdx.x] += t;
        __syncthreads();
    }
    g_bspine[threadIdx.x] = s[threadIdx.x] - v;
    if (threadIdx.x == SCAN_B - 1) g_off[n] = s[threadIdx.x];  // total edges
}
__global__ void k_scan_add(int n) {
    int i = blockIdx.x * blockDim.x + threadIdx.x;
    if (i >= n) return;
    int o = g_off[i] + g_bspine[i >> 8];
    g_off[i] = o;
    g_cursor[i] = o;
    g_dinv[i] = rsqrtf((float)g_hist[i] + 1.0f);   // +1 self loop
}
__global__ void k_reorder(const void* __restrict__ ei, int E, int n) {
    int e = blockIdx.x * blockDim.x + threadIdx.x;
    if (e >= E) return;
    int is64 = g_is64;
    long long s = load_idx(ei, e, is64);
    long long d = load_idx(ei, (long long)E + e, is64);
    if ((unsigned long long)d >= (unsigned long long)n) return;
    int pos = atomicAdd(&g_cursor[d], 1);
    int sv = ((unsigned long long)s < (unsigned long long)n) ? (int)s : (int)d;
    g_csr[pos] = sv;
}

// ---------------- xs = x * dinv[row] ----------------------------------------
__global__ void k_scale(const float* __restrict__ x, int n) {
    int t = blockIdx.x * blockDim.x + threadIdx.x;
    int total = n * (D / 4);
    if (t >= total) return;
    int row = t >> 6;
    float s = g_dinv[row];
    float4 v = reinterpret_cast<const float4*>(x)[t];
    v.x *= s; v.y *= s; v.z *= s; v.w *= s;
    g_xs4[t] = v;
}

// ---------------- fused gather + norm + bf16 split --------------------------
// One warp per node row. agg = xs[r] + sum_e xs[csr[e]];  z = dinv[r]*agg;
// split z into bf16 hi/lo planes g_Ah/g_Al. Rows >= N written as zeros.
__global__ __launch_bounds__(256)
void k_gather(int M) {
    int warp = (blockIdx.x * blockDim.x + threadIdx.x) >> 5;
    int lane = threadIdx.x & 31;
    if (warp >= MP) return;
    int r = warp;

    union { __nv_bfloat16 h[4]; uint2 v; } p0h, p0l, p1h, p1l;

    if (r < M) {
        size_t base = (size_t)r * 64;
        float4 a0 = g_xs4[base + lane];        // cols 4L..4L+3
        float4 a1 = g_xs4[base + lane + 32];   // cols 128+4L..
        int beg = g_off[r];
        int end = g_off[r + 1];
#pragma unroll 4
        for (int e = beg; e < end; e++) {
            int s = __ldg(&g_csr[e]);
            size_t sb = (size_t)s * 64;
            float4 u0 = g_xs4[sb + lane];
            float4 u1 = g_xs4[sb + lane + 32];
            a0.x += u0.x; a0.y += u0.y; a0.z += u0.z; a0.w += u0.w;
            a1.x += u1.x; a1.y += u1.y; a1.z += u1.z; a1.w += u1.w;
        }
        float dv = g_dinv[r];
        float f0[4] = {a0.x * dv, a0.y * dv, a0.z * dv, a0.w * dv};
        float f1[4] = {a1.x * dv, a1.y * dv, a1.z * dv, a1.w * dv};
#pragma unroll
        for (int e = 0; e < 4; e++) {
            p0h.h[e] = __float2bfloat16(f0[e]);
            p0l.h[e] = __float2bfloat16(f0[e] - __bfloat162float(p0h.h[e]));
            p1h.h[e] = __float2bfloat16(f1[e]);
            p1l.h[e] = __float2bfloat16(f1[e] - __bfloat162float(p1h.h[e]));
        }
    } else {
        p0h.v = make_uint2(0, 0); p0l.v = p0h.v;
        p1h.v = p0h.v;            p1l.v = p0h.v;
    }
    // row r, cols [4L,4L+3] and [128+4L, 128+4L+3] : 8B stores
    char* ah = (char*)(g_Ah + (size_t)r * D);
    char* al = (char*)(g_Al + (size_t)r * D);
    *reinterpret_cast<uint2*>(ah + lane * 8)       = p0h.v;
    *reinterpret_cast<uint2*>(ah + 256 + lane * 8) = p1h.v;
    *reinterpret_cast<uint2*>(al + lane * 8)       = p0l.v;
    *reinterpret_cast<uint2*>(al + 256 + lane * 8) = p1l.v;
}

// ---------------- B prep: interleaved [W1|W2] split into bf16 hi/lo ---------
__global__ void k_prep_B(const float* __restrict__ W1, const float* __restrict__ W2) {
    int n = blockIdx.x;       // 0..511
    int k = threadIdx.x;      // 0..255
    int j = n >> 7, l = n & 127;
    const float* W = (l < 64) ? W1 : W2;
    int col = j * 64 + (l & 63);
    float w = W[k * D + col];
    __nv_bfloat16 hi = __float2bfloat16(w);
    float lo = w - __bfloat162float(hi);
    g_Bh[n * D + k] = hi;
    g_Bl[n * D + k] = __float2bfloat16(lo);
}

// ---------------- mma.sync bf16 helper --------------------------------------
__device__ __forceinline__ void mma16816(float c[4], const uint32_t a[4],
                                         const uint32_t b[2]) {
    asm volatile(
        "mma.sync.aligned.m16n8k16.row.col.f32.bf16.bf16.f32 "
        "{%0,%1,%2,%3}, {%4,%5,%6,%7}, {%8,%9}, {%0,%1,%2,%3};"
        : "+f"(c[0]), "+f"(c[1]), "+f"(c[2]), "+f"(c[3])
        : "r"(a[0]), "r"(a[1]), "r"(a[2]), "r"(a[3]), "r"(b[0]), "r"(b[1]));
}

// ---------------- HMMA split-bf16 dual GEMM + fused epilogue ----------------
#define PITCH 40   // smem row pitch in bf16 elements (80B = 20 banks, 16B-aligned)

__global__ __launch_bounds__(256)
void k_gemm_mma(const float* __restrict__ b1, const float* __restrict__ b2,
                float* __restrict__ out, int M) {
    __shared__ uint16_t AsH[128 * PITCH];
    __shared__ uint16_t AsL[128 * PITCH];
    __shared__ uint16_t Bs[4][64 * PITCH];   // [0]=W1h [1]=W1l [2]=W2h [3]=W2l

    int tid = threadIdx.x;
    int wid = tid >> 5;
    int lane = tid & 31;
    int wm = wid >> 1;           // 0..3  (rows wm*32)
    int wn = wid & 1;            // 0..1  (cols wn*32)
    int g = lane >> 2;           // 0..7
    int tig = lane & 3;          // 0..3
    int rowBase = blockIdx.x * 128;
    int j = blockIdx.y;          // col tile 0..3
    int cb = j * 64;

    float acc1[2][4][4] = {};
    float acc2[2][4][4] = {};

    const uint4* Ah4 = reinterpret_cast<const uint4*>(g_Ah);
    const uint4* Al4 = reinterpret_cast<const uint4*>(g_Al);
    const uint4* Bh4 = reinterpret_cast<const uint4*>(g_Bh);
    const uint4* Bl4 = reinterpret_cast<const uint4*>(g_Bl);

    for (int k0 = 0; k0 < D; k0 += 32) {
#pragma unroll
        for (int it = 0; it < 2; it++) {
            int idx = tid + it * 256;
            int r = idx >> 2;
            int kg = idx & 3;
            uint4 vh = Ah4[(size_t)(rowBase + r) * 32 + (k0 >> 3) + kg];
            uint4 vl = Al4[(size_t)(rowBase + r) * 32 + (k0 >> 3) + kg];
            *reinterpret_cast<uint4*>(&AsH[r * PITCH + kg * 8]) = vh;
            *reinterpret_cast<uint4*>(&AsL[r * PITCH + kg * 8]) = vl;
        }
        {
            int r = tid >> 2;
            int kg = tid & 3;
            int n1 = j * 128 + r;
            int n2 = j * 128 + 64 + r;
            uint4 w1h = Bh4[(size_t)n1 * 32 + (k0 >> 3) + kg];
            uint4 w1l = Bl4[(size_t)n1 * 32 + (k0 >> 3) + kg];
            uint4 w2h = Bh4[(size_t)n2 * 32 + (k0 >> 3) + kg];
            uint4 w2l = Bl4[(size_t)n2 * 32 + (k0 >> 3) + kg];
            *reinterpret_cast<uint4*>(&Bs[0][r * PITCH + kg * 8]) = w1h;
            *reinterpret_cast<uint4*>(&Bs[1][r * PITCH + kg * 8]) = w1l;
            *reinterpret_cast<uint4*>(&Bs[2][r * PITCH + kg * 8]) = w2h;
            *reinterpret_cast<uint4*>(&Bs[3][r * PITCH + kg * 8]) = w2l;
        }
        __syncthreads();

#pragma unroll
        for (int ks = 0; ks < 2; ks++) {
            int kb = ks * 16;
            uint32_t ah[2][4], al[2][4];
#pragma unroll
            for (int mb = 0; mb < 2; mb++) {
                int r = wm * 32 + mb * 16 + g;
                const uint16_t* pH = &AsH[r * PITCH + kb + tig * 2];
                const uint16_t* pL = &AsL[r * PITCH + kb + tig * 2];
                ah[mb][0] = *(const uint32_t*)pH;
                ah[mb][1] = *(const uint32_t*)(pH + 8 * PITCH);
                ah[mb][2] = *(const uint32_t*)(pH + 8);
                ah[mb][3] = *(const uint32_t*)(pH + 8 * PITCH + 8);
                al[mb][0] = *(const uint32_t*)pL;
                al[mb][1] = *(const uint32_t*)(pL + 8 * PITCH);
                al[mb][2] = *(const uint32_t*)(pL + 8);
                al[mb][3] = *(const uint32_t*)(pL + 8 * PITCH + 8);
            }
            uint32_t b1h[4][2], b1l[4][2], b2h[4][2], b2l[4][2];
#pragma unroll
            for (int nb = 0; nb < 4; nb++) {
                int n = wn * 32 + nb * 8 + g;
                int o = n * PITCH + kb + tig * 2;
                b1h[nb][0] = *(const uint32_t*)&Bs[0][o];
                b1h[nb][1] = *(const uint32_t*)&Bs[0][o + 8];
                b1l[nb][0] = *(const uint32_t*)&Bs[1][o];
                b1l[nb][1] = *(const uint32_t*)&Bs[1][o + 8];
                b2h[nb][0] = *(const uint32_t*)&Bs[2][o];
                b2h[nb][1] = *(const uint32_t*)&Bs[2][o + 8];
                b2l[nb][0] = *(const uint32_t*)&Bs[3][o];
                b2l[nb][1] = *(const uint32_t*)&Bs[3][o + 8];
            }
#pragma unroll
            for (int mb = 0; mb < 2; mb++)
#pragma unroll
                for (int nb = 0; nb < 4; nb++) {
                    mma16816(acc1[mb][nb], ah[mb], b1h[nb]);
                    mma16816(acc1[mb][nb], ah[mb], b1l[nb]);
                    mma16816(acc1[mb][nb], al[mb], b1h[nb]);
                    mma16816(acc2[mb][nb], ah[mb], b2h[nb]);
                    mma16816(acc2[mb][nb], ah[mb], b2l[nb]);
                    mma16816(acc2[mb][nb], al[mb], b2h[nb]);
                }
        }
        __syncthreads();
    }

#pragma unroll
    for (int mb = 0; mb < 2; mb++) {
#pragma unroll
        for (int nb = 0; nb < 4; nb++) {
            int c = cb + wn * 32 + nb * 8 + tig * 2;
            float bb1a = __ldg(&b1[c]), bb1b = __ldg(&b1[c + 1]);
            float bb2a = __ldg(&b2[c]), bb2b = __ldg(&b2[c + 1]);
#pragma unroll
            for (int h = 0; h < 2; h++) {
                int r = rowBase + wm * 32 + mb * 16 + g + h * 8;
                if (r >= M) continue;
                float z1 = acc1[mb][nb][h * 2]     + bb1a;
                float z2 = acc1[mb][nb][h * 2 + 1] + bb1b;
                z1 = z1 > 0.0f ? z1 : 0.0f;
                z2 = z2 > 0.0f ? z2 : 0.0f;
                float2 o;
                o.x = z1 + acc2[mb][nb][h * 2]     + bb2a;
                o.y = z2 + acc2[mb][nb][h * 2 + 1] + bb2b;
                *reinterpret_cast<float2*>(out + (size_t)r * D + c) = o;
            }
        }
    }
}

// ---------------- launch ----------------
extern "C" void kernel_launch(void* const* d_in, const int* in_sizes, int n_in,
                              void* d_out, int out_size) {
    const float* x  = (const float*)d_in[0];
    const void*  ei = d_in[1];
    const float* W1 = (const float*)d_in[2];
    const float* b1 = (const float*)d_in[3];
    const float* W2 = (const float*)d_in[4];
    const float* b2 = (const float*)d_in[5];
    float* out      = (float*)d_out;

    int N = in_sizes[0] / D;   // 50000
    int E = in_sizes[1] / 2;   // 800000
    int nb = (N + SCAN_B - 1) / SCAN_B;   // 196

    k_detect<<<1, 256>>>((const int*)ei);
    k_zero_hist<<<(N + 255) / 256, 256>>>(N);
    k_hist<<<(E + 255) / 256, 256>>>(ei, E, N);
    k_scan_block<<<nb, SCAN_B>>>(N);
    k_scan_spine<<<1, SCAN_B>>>(nb, N);
    k_scan_add<<<nb, SCAN_B>>>(N);
    k_scale<<<(N * (D / 4) + 255) / 256, 256>>>(x, N);
    k_reorder<<<(E + 255) / 256, 256>>>(ei, E, N);
    k_prep_B<<<NB, 256>>>(W1, W2);

    k_gather<<<(MP * 32 + 255) / 256, 256>>>(N);

    dim3 grid(MP / 128, 4);
    k_gemm_mma<<<grid, 256>>>(b1, b2, out, N);
}

// round 7
// speedup vs baseline: 2.3860x; 1.1344x over previous
#include <cuda_runtime.h>
#include <cuda_bf16.h>
#include <cstdint>

#define D 256
#define MAXN 50000
#define MP 50048            // M padded to multiple of 128
#define NB 512              // fused B rows (W1|W2 interleaved by n-tile)
#define MAXE 800000
#define SCAN_B 256

// ---------------- scratch (__device__ globals; allocation-free rule) --------
__device__ float  g_dinv[MAXN];
__device__ int    g_hist[MAXN];
__device__ int    g_off[MAXN + 1];
__device__ int    g_cursor[MAXN];
__device__ int    g_csr[MAXE];
__device__ int    g_bsum[256];
__device__ int    g_bspine[256];
__device__ int    g_is64;
__device__ __nv_bfloat16 g_Ah[MP * D];   // z hi (z = dinv*agg), padded w/ zeros
__device__ __nv_bfloat16 g_Al[MP * D];   // z lo
__device__ __nv_bfloat16 g_Bh[NB * D];   // fused W hi  [n][k]
__device__ __nv_bfloat16 g_Bl[NB * D];   // fused W lo  [n][k]

// ---------------- init: zero hist + edge dtype detection --------------------
__global__ void k_init(const int* __restrict__ w, int n) {
    int i = blockIdx.x * blockDim.x + threadIdx.x;
    if (i < n) g_hist[i] = 0;
    if (blockIdx.x == 0) {
        __shared__ int s[256];
        int acc = 0;
        for (int k = threadIdx.x * 2 + 1; k < 4096; k += 512) acc |= w[k];
        s[threadIdx.x] = acc;
        __syncthreads();
        for (int o = 128; o > 0; o >>= 1) {
            if (threadIdx.x < o) s[threadIdx.x] |= s[threadIdx.x + o];
            __syncthreads();
        }
        if (threadIdx.x == 0) g_is64 = (s[0] == 0) ? 1 : 0;
    }
}

__device__ __forceinline__ long long load_idx(const void* ei, long long pos, int is64) {
    if (is64) return ((const long long*)ei)[pos];
    return (long long)((const int*)ei)[pos];
}

// ---------------- CSR build --------------------------------------------------
__global__ void k_hist(const void* __restrict__ ei, int E, int n) {
    int e = blockIdx.x * blockDim.x + threadIdx.x;
    if (e >= E) return;
    long long dst = load_idx(ei, (long long)E + e, g_is64);
    if ((unsigned long long)dst < (unsigned long long)n)
        atomicAdd(&g_hist[dst], 1);
}
__global__ void k_scan_block(int n) {
    __shared__ int s[SCAN_B];
    int i = blockIdx.x * SCAN_B + threadIdx.x;
    int v = (i < n) ? g_hist[i] : 0;
    s[threadIdx.x] = v;
    __syncthreads();
#pragma unroll
    for (int o = 1; o < SCAN_B; o <<= 1) {
        int t = (threadIdx.x >= o) ? s[threadIdx.x - o] : 0;
        __syncthreads();
        s[threadIdx.x] += t;
        __syncthreads();
    }
    if (i < n) g_off[i] = s[threadIdx.x] - v;
    if (threadIdx.x == SCAN_B - 1) g_bsum[blockIdx.x] = s[threadIdx.x];
}
__global__ void k_scan_spine(int nb, int n) {
    __shared__ int s[SCAN_B];
    int v = (threadIdx.x < nb) ? g_bsum[threadIdx.x] : 0;
    s[threadIdx.x] = v;
    __syncthreads();
#pragma unroll
    for (int o = 1; o < SCAN_B; o <<= 1) {
        int t = (threadIdx.x >= o) ? s[threadIdx.x - o] : 0;
        __syncthreads();
        s[threadIdx.x] += t;
        __syncthreads();
    }
    g_bspine[threadIdx.x] = s[threadIdx.x] - v;
    if (threadIdx.x == SCAN_B - 1) g_off[n] = s[threadIdx.x];
}
__global__ void k_scan_add(int n) {
    int i = blockIdx.x * blockDim.x + threadIdx.x;
    if (i >= n) return;
    int o = g_off[i] + g_bspine[i >> 8];
    g_off[i] = o;
    g_cursor[i] = o;
    g_dinv[i] = rsqrtf((float)g_hist[i] + 1.0f);   // +1 self loop
}
__global__ void k_reorder(const void* __restrict__ ei, int E, int n) {
    int e = blockIdx.x * blockDim.x + threadIdx.x;
    if (e >= E) return;
    int is64 = g_is64;
    long long s = load_idx(ei, e, is64);
    long long d = load_idx(ei, (long long)E + e, is64);
    if ((unsigned long long)d >= (unsigned long long)n) return;
    int pos = atomicAdd(&g_cursor[d], 1);
    int sv = ((unsigned long long)s < (unsigned long long)n) ? (int)s : (int)d;
    g_csr[pos] = sv;
}

// ---------------- fused gather + norm + bf16 split --------------------------
// One warp per node row r:
//   agg = dinv[r]*x[r] + sum_e dinv[s]*x[s];  z = dinv[r]*agg
// split z into bf16 hi/lo planes g_Ah/g_Al. Rows >= N written as zeros.
__global__ __launch_bounds__(256)
void k_gather(const float* __restrict__ x, int M) {
    int warp = (blockIdx.x * blockDim.x + threadIdx.x) >> 5;
    int lane = threadIdx.x & 31;
    if (warp >= MP) return;
    int r = warp;

    union { __nv_bfloat16 h[4]; uint2 v; } p0h, p0l, p1h, p1l;

    if (r < M) {
        const float4* x4 = reinterpret_cast<const float4*>(x);
        float dv = g_dinv[r];
        size_t base = (size_t)r * 64;
        float4 a0 = x4[base + lane];
        float4 a1 = x4[base + lane + 32];
        a0.x *= dv; a0.y *= dv; a0.z *= dv; a0.w *= dv;
        a1.x *= dv; a1.y *= dv; a1.z *= dv; a1.w *= dv;
        int beg = g_off[r];
        int end = g_off[r + 1];
#pragma unroll 4
        for (int e = beg; e < end; e++) {
            int s = __ldg(&g_csr[e]);
            float ds = __ldg(&g_dinv[s]);
            size_t sb = (size_t)s * 64;
            float4 u0 = x4[sb + lane];
            float4 u1 = x4[sb + lane + 32];
            a0.x = fmaf(u0.x, ds, a0.x); a0.y = fmaf(u0.y, ds, a0.y);
            a0.z = fmaf(u0.z, ds, a0.z); a0.w = fmaf(u0.w, ds, a0.w);
            a1.x = fmaf(u1.x, ds, a1.x); a1.y = fmaf(u1.y, ds, a1.y);
            a1.z = fmaf(u1.z, ds, a1.z); a1.w = fmaf(u1.w, ds, a1.w);
        }
        float f0[4] = {a0.x * dv, a0.y * dv, a0.z * dv, a0.w * dv};
        float f1[4] = {a1.x * dv, a1.y * dv, a1.z * dv, a1.w * dv};
#pragma unroll
        for (int e = 0; e < 4; e++) {
            p0h.h[e] = __float2bfloat16(f0[e]);
            p0l.h[e] = __float2bfloat16(f0[e] - __bfloat162float(p0h.h[e]));
            p1h.h[e] = __float2bfloat16(f1[e]);
            p1l.h[e] = __float2bfloat16(f1[e] - __bfloat162float(p1h.h[e]));
        }
    } else {
        p0h.v = make_uint2(0, 0); p0l.v = p0h.v;
        p1h.v = p0h.v;            p1l.v = p0h.v;
    }
    char* ah = (char*)(g_Ah + (size_t)r * D);
    char* al = (char*)(g_Al + (size_t)r * D);
    *reinterpret_cast<uint2*>(ah + lane * 8)       = p0h.v;
    *reinterpret_cast<uint2*>(ah + 256 + lane * 8) = p1h.v;
    *reinterpret_cast<uint2*>(al + lane * 8)       = p0l.v;
    *reinterpret_cast<uint2*>(al + 256 + lane * 8) = p1l.v;
}

// ---------------- B prep: interleaved [W1|W2] split into bf16 hi/lo ---------
__global__ void k_prep_B(const float* __restrict__ W1, const float* __restrict__ W2) {
    int n = blockIdx.x;       // 0..511
    int k = threadIdx.x;      // 0..255
    int j = n >> 7, l = n & 127;
    const float* W = (l < 64) ? W1 : W2;
    int col = j * 64 + (l & 63);
    float w = W[k * D + col];
    __nv_bfloat16 hi = __float2bfloat16(w);
    float lo = w - __bfloat162float(hi);
    g_Bh[n * D + k] = hi;
    g_Bl[n * D + k] = __float2bfloat16(lo);
}

// ---------------- mma / async helpers ---------------------------------------
__device__ __forceinline__ void mma16816(float c[4], const uint32_t a[4],
                                         const uint32_t b[2]) {
    asm volatile(
        "mma.sync.aligned.m16n8k16.row.col.f32.bf16.bf16.f32 "
        "{%0,%1,%2,%3}, {%4,%5,%6,%7}, {%8,%9}, {%0,%1,%2,%3};"
        : "+f"(c[0]), "+f"(c[1]), "+f"(c[2]), "+f"(c[3])
        : "r"(a[0]), "r"(a[1]), "r"(a[2]), "r"(a[3]), "r"(b[0]), "r"(b[1]));
}
__device__ __forceinline__ void cp16(uint32_t saddr, const void* g) {
    asm volatile("cp.async.cg.shared.global [%0], [%1], 16;"
                 :: "r"(saddr), "l"(g) : "memory");
}
__device__ __forceinline__ void cp_commit() {
    asm volatile("cp.async.commit_group;" ::: "memory");
}
__device__ __forceinline__ void ldsm_x4(uint32_t& r0, uint32_t& r1,
                                        uint32_t& r2, uint32_t& r3, uint32_t a) {
    asm volatile("ldmatrix.sync.aligned.m8n8.x4.shared.b16 {%0,%1,%2,%3}, [%4];"
                 : "=r"(r0), "=r"(r1), "=r"(r2), "=r"(r3) : "r"(a));
}
__device__ __forceinline__ uint32_t smem_u32(const void* p) {
    uint32_t a;
    asm("{ .reg .u64 t; cvta.to.shared.u64 t, %1; cvt.u32.u64 %0, t; }"
        : "=r"(a) : "l"(p));
    return a;
}

// ---------------- HMMA split-bf16 dual GEMM, cp.async 2-stage ---------------
// smem (halfs): A[stage][plane][128*40] then B[stage][plane4][64*40]
#define PITCH 40
#define A_PLANE (128 * PITCH)                 // 5120 halfs
#define B_PLANE (64 * PITCH)                  // 2560 halfs
#define B_BASE  (4 * A_PLANE)                 // after 2 stages x 2 planes
#define SM_HALFS (B_BASE + 8 * B_PLANE)       // 40960 halfs = 80 KB

__global__ __launch_bounds__(256, 1)
void k_gemm_mma(const float* __restrict__ b1, const float* __restrict__ b2,
                float* __restrict__ out, int M) {
    extern __shared__ uint16_t sm[];
    uint32_t sb = smem_u32(sm);

    int tid = threadIdx.x;
    int wid = tid >> 5;
    int lane = tid & 31;
    int wm = wid >> 1;
    int wn = wid & 1;
    int g = lane >> 2;
    int tig = lane & 3;
    int rowBase = blockIdx.x * 128;
    int j = blockIdx.y;
    int cb = j * 64;

    float acc1[2][4][4] = {};
    float acc2[2][4][4] = {};

    const uint4* Ah4 = reinterpret_cast<const uint4*>(g_Ah);
    const uint4* Al4 = reinterpret_cast<const uint4*>(g_Al);
    const uint4* Bh4 = reinterpret_cast<const uint4*>(g_Bh);
    const uint4* Bl4 = reinterpret_cast<const uint4*>(g_Bl);

    // per-thread load coords
    int lr = tid >> 2;           // 0..63  (A: pairs to 2 rows; B: row)
    int lkg = tid & 3;           // 16B chunk within 64B row

    // issue one stage's loads (k-chunk kc = stage index in K)
    auto issue = [&](int kc, int st) {
        int kb4 = kc * 4;        // uint4 offset in row of 32 halfs
        // A: 128 rows x 4 chunks, 2 planes
#pragma unroll
        for (int it = 0; it < 2; it++) {
            int r = lr + it * 64;
            uint32_t sa = sb + ((st * 2) * A_PLANE + r * PITCH + lkg * 8) * 2;
            cp16(sa, &Ah4[(size_t)(rowBase + r) * 32 + kb4 + lkg]);
            uint32_t sl = sb + ((st * 2 + 1) * A_PLANE + r * PITCH + lkg * 8) * 2;
            cp16(sl, &Al4[(size_t)(rowBase + r) * 32 + kb4 + lkg]);
        }
        // B: 4 planes x 64 rows x 4 chunks
        int n1 = j * 128 + lr;
        int n2 = n1 + 64;
        uint32_t bo = sb + (B_BASE + (st * 4) * B_PLANE + lr * PITCH + lkg * 8) * 2;
        cp16(bo,                 &Bh4[(size_t)n1 * 32 + kb4 + lkg]);
        cp16(bo + B_PLANE * 2,   &Bl4[(size_t)n1 * 32 + kb4 + lkg]);
        cp16(bo + B_PLANE * 4,   &Bh4[(size_t)n2 * 32 + kb4 + lkg]);
        cp16(bo + B_PLANE * 6,   &Bl4[(size_t)n2 * 32 + kb4 + lkg]);
        cp_commit();
    };

    issue(0, 0);

    // ldmatrix address templates
    int aRowSel = lane & 15;
    int aColSel = (lane >> 4) << 3;           // 0 or 8 (halfs)
    int bm = lane >> 3;                       // 0..3
    int bRowSel = ((bm >> 1) << 3) + (lane & 7);
    int bColSel = (bm & 1) << 3;

    for (int kc = 0; kc < 8; kc++) {
        int st = kc & 1;
        if (kc < 7) issue(kc + 1, st ^ 1);
        if (kc < 7) asm volatile("cp.async.wait_group 1;" ::: "memory");
        else        asm volatile("cp.async.wait_group 0;" ::: "memory");
        __syncthreads();

        uint32_t aH = sb + ((st * 2) * A_PLANE) * 2;
        uint32_t aL = aH + A_PLANE * 2;
        uint32_t bBase = sb + (B_BASE + (st * 4) * B_PLANE) * 2;

#pragma unroll
        for (int ks = 0; ks < 2; ks++) {
            int kb = ks * 16;
            uint32_t ah[2][4], al[2][4];
#pragma unroll
            for (int mb = 0; mb < 2; mb++) {
                int row = wm * 32 + mb * 16 + aRowSel;
                uint32_t off = (row * PITCH + kb + aColSel) * 2;
                ldsm_x4(ah[mb][0], ah[mb][1], ah[mb][2], ah[mb][3], aH + off);
                ldsm_x4(al[mb][0], al[mb][1], al[mb][2], al[mb][3], aL + off);
            }
            uint32_t bf[4][4][2];   // [plane][nb][2]
#pragma unroll
            for (int p = 0; p < 4; p++) {
#pragma unroll
                for (int q = 0; q < 2; q++) {
                    int n = wn * 32 + q * 16 + bRowSel;
                    uint32_t addr = bBase + p * B_PLANE * 2 +
                                    (n * PITCH + kb + bColSel) * 2;
                    ldsm_x4(bf[p][q * 2][0], bf[p][q * 2][1],
                            bf[p][q * 2 + 1][0], bf[p][q * 2 + 1][1], addr);
                }
            }
#pragma unroll
            for (int mb = 0; mb < 2; mb++)
#pragma unroll
                for (int nb = 0; nb < 4; nb++) {
                    mma16816(acc1[mb][nb], ah[mb], bf[0][nb]);
                    mma16816(acc1[mb][nb], ah[mb], bf[1][nb]);
                    mma16816(acc1[mb][nb], al[mb], bf[0][nb]);
                    mma16816(acc2[mb][nb], ah[mb], bf[2][nb]);
                    mma16816(acc2[mb][nb], ah[mb], bf[3][nb]);
                    mma16816(acc2[mb][nb], al[mb], bf[2][nb]);
                }
        }
        __syncthreads();
    }

    // ---- epilogue: out = relu(acc1 + b1) + acc2 + b2 ----
#pragma unroll
    for (int mb = 0; mb < 2; mb++) {
#pragma unroll
        for (int nb = 0; nb < 4; nb++) {
            int c = cb + wn * 32 + nb * 8 + tig * 2;
            float bb1a = __ldg(&b1[c]), bb1b = __ldg(&b1[c + 1]);
            float bb2a = __ldg(&b2[c]), bb2b = __ldg(&b2[c + 1]);
#pragma unroll
            for (int h = 0; h < 2; h++) {
                int r = rowBase + wm * 32 + mb * 16 + g + h * 8;
                if (r >= M) continue;
                float z1 = acc1[mb][nb][h * 2]     + bb1a;
                float z2 = acc1[mb][nb][h * 2 + 1] + bb1b;
                z1 = z1 > 0.0f ? z1 : 0.0f;
                z2 = z2 > 0.0f ? z2 : 0.0f;
                float2 o;
                o.x = z1 + acc2[mb][nb][h * 2]     + bb2a;
                o.y = z2 + acc2[mb][nb][h * 2 + 1] + bb2b;
                *reinterpret_cast<float2*>(out + (size_t)r * D + c) = o;
            }
        }
    }
}

// ---------------- launch ----------------
extern "C" void kernel_launch(void* const* d_in, const int* in_sizes, int n_in,
                              void* d_out, int out_size) {
    const float* x  = (const float*)d_in[0];
    const void*  ei = d_in[1];
    const float* W1 = (const float*)d_in[2];
    const float* b1 = (const float*)d_in[3];
    const float* W2 = (const float*)d_in[4];
    const float* b2 = (const float*)d_in[5];
    float* out      = (float*)d_out;

    int N = in_sizes[0] / D;   // 50000
    int E = in_sizes[1] / 2;   // 800000
    int nb = (N + SCAN_B - 1) / SCAN_B;   // 196

    static int smem_set = 0;
    if (!smem_set) {
        cudaFuncSetAttribute(k_gemm_mma, cudaFuncAttributeMaxDynamicSharedMemorySize,
                             SM_HALFS * 2);
        smem_set = 1;
    }

    k_init<<<(N + 255) / 256, 256>>>((const int*)ei, N);
    k_hist<<<(E + 255) / 256, 256>>>(ei, E, N);
    k_scan_block<<<nb, SCAN_B>>>(N);
    k_scan_spine<<<1, SCAN_B>>>(nb, N);
    k_scan_add<<<nb, SCAN_B>>>(N);
    k_reorder<<<(E + 255) / 256, 256>>>(ei, E, N);
    k_prep_B<<<NB, 256>>>(W1, W2);

    k_gather<<<(MP * 32 + 255) / 256, 256>>>(x, N);

    dim3 grid(MP / 128, 4);
    k_gemm_mma<<<grid, 256, SM_HALFS * 2>>>(b1, b2, out, N);
}

// round 8
// speedup vs baseline: 3.2682x; 1.3697x over previous
#include <cuda_runtime.h>
#include <cuda_fp16.h>
#include <cstdint>

#define D 256
#define MAXN 50000
#define MP 50048            // M padded to multiple of 128
#define NB 512              // fused B rows (W1|W2 interleaved by n-tile)
#define MAXE 800000
#define SCAN_B 256

// ---------------- scratch (__device__ globals; allocation-free rule) --------
__device__ float  g_dinv[MAXN];
__device__ int    g_hist[MAXN];
__device__ int    g_off[MAXN + 1];
__device__ int    g_cursor[MAXN];
__device__ int    g_csr[MAXE];
__device__ int    g_bsum[256];
__device__ int    g_is64;
__device__ __half g_Ah[MP * D];   // z hi (fp16), padded w/ zeros
__device__ __half g_Al[MP * D];   // z lo (fp16 residual)
__device__ __half g_B[NB * D];    // fused W (fp16) [n][k]

// ---------------- init: zero hist + dtype detect + B prep (fused) -----------
__global__ void k_init(const int* __restrict__ w, const float* __restrict__ W1,
                       const float* __restrict__ W2, int n, int nhb) {
    int b = blockIdx.x;
    if (b < nhb) {
        int i = b * blockDim.x + threadIdx.x;
        if (i < n) g_hist[i] = 0;
        if (b == 0) {
            __shared__ int s[256];
            int acc = 0;
            for (int k = threadIdx.x * 2 + 1; k < 4096; k += 512) acc |= w[k];
            s[threadIdx.x] = acc;
            __syncthreads();
            for (int o = 128; o > 0; o >>= 1) {
                if (threadIdx.x < o) s[threadIdx.x] |= s[threadIdx.x + o];
                __syncthreads();
            }
            if (threadIdx.x == 0) g_is64 = (s[0] == 0) ? 1 : 0;
        }
    } else {
        // B prep: row nrow = j*128 + l; l<64 -> W1 col j*64+l, else W2
        int nrow = b - nhb;          // 0..511
        int k = threadIdx.x;         // 0..255
        int j = nrow >> 7, l = nrow & 127;
        const float* W = (l < 64) ? W1 : W2;
        int col = j * 64 + (l & 63);
        g_B[nrow * D + k] = __float2half_rn(W[k * D + col]);
    }
}

__device__ __forceinline__ long long load_idx(const void* ei, long long pos, int is64) {
    if (is64) return ((const long long*)ei)[pos];
    return (long long)((const int*)ei)[pos];
}

// ---------------- CSR build --------------------------------------------------
__global__ void k_hist(const void* __restrict__ ei, int E, int n) {
    int e = blockIdx.x * blockDim.x + threadIdx.x;
    if (e >= E) return;
    long long dst = load_idx(ei, (long long)E + e, g_is64);
    if ((unsigned long long)dst < (unsigned long long)n)
        atomicAdd(&g_hist[dst], 1);
}
__global__ void k_scan_block(int n) {
    __shared__ int s[SCAN_B];
    int i = blockIdx.x * SCAN_B + threadIdx.x;
    int v = (i < n) ? g_hist[i] : 0;
    s[threadIdx.x] = v;
    __syncthreads();
#pragma unroll
    for (int o = 1; o < SCAN_B; o <<= 1) {
        int t = (threadIdx.x >= o) ? s[threadIdx.x - o] : 0;
        __syncthreads();
        s[threadIdx.x] += t;
        __syncthreads();
    }
    if (i < n) g_off[i] = s[threadIdx.x] - v;   // block-local exclusive
    if (threadIdx.x == SCAN_B - 1) g_bsum[blockIdx.x] = s[threadIdx.x];
}
// fused spine + add: each block redundantly scans the (<=256) block sums
__global__ void k_scan_add(int n, int nb) {
    __shared__ int s[SCAN_B];
    int v = (threadIdx.x < nb) ? g_bsum[threadIdx.x] : 0;
    s[threadIdx.x] = v;
    __syncthreads();
#pragma unroll
    for (int o = 1; o < SCAN_B; o <<= 1) {
        int t = (threadIdx.x >= o) ? s[threadIdx.x - o] : 0;
        __syncthreads();
        s[threadIdx.x] += t;
        __syncthreads();
    }
    int spine = (blockIdx.x == 0) ? 0 : s[blockIdx.x - 1];
    int i = blockIdx.x * SCAN_B + threadIdx.x;
    if (i < n) {
        int o = g_off[i] + spine;
        g_off[i] = o;
        g_cursor[i] = o;
        g_dinv[i] = rsqrtf((float)g_hist[i] + 1.0f);   // +1 self loop
    }
    if (blockIdx.x == 0 && threadIdx.x == 0) g_off[n] = s[nb - 1];
}
__global__ void k_reorder(const void* __restrict__ ei, int E, int n) {
    int e = blockIdx.x * blockDim.x + threadIdx.x;
    if (e >= E) return;
    int is64 = g_is64;
    long long s = load_idx(ei, e, is64);
    long long d = load_idx(ei, (long long)E + e, is64);
    if ((unsigned long long)d >= (unsigned long long)n) return;
    int pos = atomicAdd(&g_cursor[d], 1);
    int sv = ((unsigned long long)s < (unsigned long long)n) ? (int)s : (int)d;
    g_csr[pos] = sv;
}

// ---------------- fused gather + norm + fp16 split --------------------------
// One warp per node row r:
//   agg = dinv[r]*x[r] + sum_e dinv[s]*x[s];  z = dinv[r]*agg
// split z into fp16 hi/lo planes g_Ah/g_Al. Rows >= N written as zeros.
__global__ __launch_bounds__(256)
void k_gather(const float* __restrict__ x, int M) {
    int warp = (blockIdx.x * blockDim.x + threadIdx.x) >> 5;
    int lane = threadIdx.x & 31;
    if (warp >= MP) return;
    int r = warp;

    union { __half h[4]; uint2 v; } p0h, p0l, p1h, p1l;

    if (r < M) {
        const float4* x4 = reinterpret_cast<const float4*>(x);
        float dv = g_dinv[r];
        size_t base = (size_t)r * 64;
        float4 a0 = x4[base + lane];
        float4 a1 = x4[base + lane + 32];
        a0.x *= dv; a0.y *= dv; a0.z *= dv; a0.w *= dv;
        a1.x *= dv; a1.y *= dv; a1.z *= dv; a1.w *= dv;
        int beg = g_off[r];
        int end = g_off[r + 1];
#pragma unroll 4
        for (int e = beg; e < end; e++) {
            int s = __ldg(&g_csr[e]);
            float ds = __ldg(&g_dinv[s]);
            size_t sb = (size_t)s * 64;
            float4 u0 = x4[sb + lane];
            float4 u1 = x4[sb + lane + 32];
            a0.x = fmaf(u0.x, ds, a0.x); a0.y = fmaf(u0.y, ds, a0.y);
            a0.z = fmaf(u0.z, ds, a0.z); a0.w = fmaf(u0.w, ds, a0.w);
            a1.x = fmaf(u1.x, ds, a1.x); a1.y = fmaf(u1.y, ds, a1.y);
            a1.z = fmaf(u1.z, ds, a1.z); a1.w = fmaf(u1.w, ds, a1.w);
        }
        float f0[4] = {a0.x * dv, a0.y * dv, a0.z * dv, a0.w * dv};
        float f1[4] = {a1.x * dv, a1.y * dv, a1.z * dv, a1.w * dv};
#pragma unroll
        for (int e = 0; e < 4; e++) {
            p0h.h[e] = __float2half_rn(f0[e]);
            p0l.h[e] = __float2half_rn(f0[e] - __half2float(p0h.h[e]));
            p1h.h[e] = __float2half_rn(f1[e]);
            p1l.h[e] = __float2half_rn(f1[e] - __half2float(p1h.h[e]));
        }
    } else {
        p0h.v = make_uint2(0, 0); p0l.v = p0h.v;
        p1h.v = p0h.v;            p1l.v = p0h.v;
    }
    char* ah = (char*)(g_Ah + (size_t)r * D);
    char* al = (char*)(g_Al + (size_t)r * D);
    *reinterpret_cast<uint2*>(ah + lane * 8)       = p0h.v;
    *reinterpret_cast<uint2*>(ah + 256 + lane * 8) = p1h.v;
    *reinterpret_cast<uint2*>(al + lane * 8)       = p0l.v;
    *reinterpret_cast<uint2*>(al + 256 + lane * 8) = p1l.v;
}

// ---------------- mma / async helpers ---------------------------------------
__device__ __forceinline__ void mma16816(float c[4], const uint32_t a[4],
                                         const uint32_t b[2]) {
    asm volatile(
        "mma.sync.aligned.m16n8k16.row.col.f32.f16.f16.f32 "
        "{%0,%1,%2,%3}, {%4,%5,%6,%7}, {%8,%9}, {%0,%1,%2,%3};"
        : "+f"(c[0]), "+f"(c[1]), "+f"(c[2]), "+f"(c[3])
        : "r"(a[0]), "r"(a[1]), "r"(a[2]), "r"(a[3]), "r"(b[0]), "r"(b[1]));
}
__device__ __forceinline__ void cp16(uint32_t saddr, const void* g) {
    asm volatile("cp.async.cg.shared.global [%0], [%1], 16;"
                 :: "r"(saddr), "l"(g) : "memory");
}
__device__ __forceinline__ void cp_commit() {
    asm volatile("cp.async.commit_group;" ::: "memory");
}
__device__ __forceinline__ void ldsm_x4(uint32_t& r0, uint32_t& r1,
                                        uint32_t& r2, uint32_t& r3, uint32_t a) {
    asm volatile("ldmatrix.sync.aligned.m8n8.x4.shared.b16 {%0,%1,%2,%3}, [%4];"
                 : "=r"(r0), "=r"(r1), "=r"(r2), "=r"(r3) : "r"(a));
}
__device__ __forceinline__ uint32_t smem_u32(const void* p) {
    uint32_t a;
    asm("{ .reg .u64 t; cvta.to.shared.u64 t, %1; cvt.u32.u64 %0, t; }"
        : "=r"(a) : "l"(p));
    return a;
}

// ---------------- HMMA fp16 2-term dual GEMM, cp.async 2-stage --------------
// smem (halfs): A[stage][plane hi/lo][128*40] then B[stage][128*40]
#define PITCH 40
#define A_PLANE (128 * PITCH)                 // 5120 halfs
#define B_STAGE (128 * PITCH)                 // 5120 halfs (64 W1 + 64 W2 rows)
#define B_BASE  (4 * A_PLANE)
#define SM_HALFS (B_BASE + 2 * B_STAGE)       // 30720 halfs = 60 KB

__global__ __launch_bounds__(256, 2)
void k_gemm_mma(const float* __restrict__ b1, const float* __restrict__ b2,
                float* __restrict__ out, int M) {
    extern __shared__ uint16_t sm[];
    uint32_t sb = smem_u32(sm);

    int tid = threadIdx.x;
    int wid = tid >> 5;
    int lane = tid & 31;
    int wm = wid >> 1;
    int wn = wid & 1;
    int g = lane >> 2;
    int tig = lane & 3;
    int rowBase = blockIdx.x * 128;
    int j = blockIdx.y;
    int cb = j * 64;

    float acc1[2][4][4] = {};
    float acc2[2][4][4] = {};

    const uint4* Ah4 = reinterpret_cast<const uint4*>(g_Ah);
    const uint4* Al4 = reinterpret_cast<const uint4*>(g_Al);
    const uint4* B4  = reinterpret_cast<const uint4*>(g_B);

    int lr = tid >> 2;           // 0..63
    int lkg = tid & 3;           // 16B chunk

    auto issue = [&](int kc, int st) {
        int kb4 = kc * 4;
#pragma unroll
        for (int it = 0; it < 2; it++) {
            int r = lr + it * 64;
            uint32_t sa = sb + ((st * 2) * A_PLANE + r * PITCH + lkg * 8) * 2;
            cp16(sa, &Ah4[(size_t)(rowBase + r) * 32 + kb4 + lkg]);
            uint32_t sl = sb + ((st * 2 + 1) * A_PLANE + r * PITCH + lkg * 8) * 2;
            cp16(sl, &Al4[(size_t)(rowBase + r) * 32 + kb4 + lkg]);
            // B: 128 rows (64 W1-cols then 64 W2-cols for this j-tile)
            uint32_t bo = sb + (B_BASE + st * B_STAGE + r * PITCH + lkg * 8) * 2;
            cp16(bo, &B4[(size_t)(j * 128 + r) * 32 + kb4 + lkg]);
        }
        cp_commit();
    };

    issue(0, 0);

    int aRowSel = lane & 15;
    int aColSel = (lane >> 4) << 3;
    int bm = lane >> 3;
    int bRowSel = ((bm >> 1) << 3) + (lane & 7);
    int bColSel = (bm & 1) << 3;

    for (int kc = 0; kc < 8; kc++) {
        int st = kc & 1;
        if (kc < 7) issue(kc + 1, st ^ 1);
        if (kc < 7) asm volatile("cp.async.wait_group 1;" ::: "memory");
        else        asm volatile("cp.async.wait_group 0;" ::: "memory");
        __syncthreads();

        uint32_t aH = sb + ((st * 2) * A_PLANE) * 2;
        uint32_t aL = aH + A_PLANE * 2;
        uint32_t bS = sb + (B_BASE + st * B_STAGE) * 2;

#pragma unroll
        for (int ks = 0; ks < 2; ks++) {
            int kb = ks * 16;
            uint32_t ah[2][4], al[2][4];
#pragma unroll
            for (int mb = 0; mb < 2; mb++) {
                int row = wm * 32 + mb * 16 + aRowSel;
                uint32_t off = (row * PITCH + kb + aColSel) * 2;
                ldsm_x4(ah[mb][0], ah[mb][1], ah[mb][2], ah[mb][3], aH + off);
                ldsm_x4(al[mb][0], al[mb][1], al[mb][2], al[mb][3], aL + off);
            }
            uint32_t bf1[4][2], bf2[4][2];
#pragma unroll
            for (int q = 0; q < 2; q++) {
                int n = wn * 32 + q * 16 + bRowSel;
                uint32_t a1 = bS + (n * PITCH + kb + bColSel) * 2;
                uint32_t a2 = bS + ((n + 64) * PITCH + kb + bColSel) * 2;
                ldsm_x4(bf1[q * 2][0], bf1[q * 2][1],
                        bf1[q * 2 + 1][0], bf1[q * 2 + 1][1], a1);
                ldsm_x4(bf2[q * 2][0], bf2[q * 2][1],
                        bf2[q * 2 + 1][0], bf2[q * 2 + 1][1], a2);
            }
#pragma unroll
            for (int mb = 0; mb < 2; mb++)
#pragma unroll
                for (int nb = 0; nb < 4; nb++) {
                    mma16816(acc1[mb][nb], ah[mb], bf1[nb]);
                    mma16816(acc1[mb][nb], al[mb], bf1[nb]);
                    mma16816(acc2[mb][nb], ah[mb], bf2[nb]);
                    mma16816(acc2[mb][nb], al[mb], bf2[nb]);
                }
        }
        __syncthreads();
    }

    // ---- epilogue: out = relu(acc1 + b1) + acc2 + b2 ----
#pragma unroll
    for (int mb = 0; mb < 2; mb++) {
#pragma unroll
        for (int nb = 0; nb < 4; nb++) {
            int c = cb + wn * 32 + nb * 8 + tig * 2;
            float bb1a = __ldg(&b1[c]), bb1b = __ldg(&b1[c + 1]);
            float bb2a = __ldg(&b2[c]), bb2b = __ldg(&b2[c + 1]);
#pragma unroll
            for (int h = 0; h < 2; h++) {
                int r = rowBase + wm * 32 + mb * 16 + g + h * 8;
                if (r >= M) continue;
                float z1 = acc1[mb][nb][h * 2]     + bb1a;
                float z2 = acc1[mb][nb][h * 2 + 1] + bb1b;
                z1 = z1 > 0.0f ? z1 : 0.0f;
                z2 = z2 > 0.0f ? z2 : 0.0f;
                float2 o;
                o.x = z1 + acc2[mb][nb][h * 2]     + bb2a;
                o.y = z2 + acc2[mb][nb][h * 2 + 1] + bb2b;
                *reinterpret_cast<float2*>(out + (size_t)r * D + c) = o;
            }
        }
    }
}

// ---------------- launch ----------------
extern "C" void kernel_launch(void* const* d_in, const int* in_sizes, int n_in,
                              void* d_out, int out_size) {
    const float* x  = (const float*)d_in[0];
    const void*  ei = d_in[1];
    const float* W1 = (const float*)d_in[2];
    const float* b1 = (const float*)d_in[3];
    const float* W2 = (const float*)d_in[4];
    const float* b2 = (const float*)d_in[5];
    float* out      = (float*)d_out;

    int N = in_sizes[0] / D;   // 50000
    int E = in_sizes[1] / 2;   // 800000
    int nb = (N + SCAN_B - 1) / SCAN_B;   // 196

    static int smem_set = 0;
    if (!smem_set) {
        cudaFuncSetAttribute(k_gemm_mma, cudaFuncAttributeMaxDynamicSharedMemorySize,
                             SM_HALFS * 2);
        smem_set = 1;
    }

    int nhb = (N + 255) / 256;
    k_init<<<nhb + NB, 256>>>((const int*)ei, W1, W2, N, nhb);
    k_hist<<<(E + 255) / 256, 256>>>(ei, E, N);
    k_scan_block<<<nb, SCAN_B>>>(N);
    k_scan_add<<<nb, SCAN_B>>>(N, nb);
    k_reorder<<<(E + 255) / 256, 256>>>(ei, E, N);

    k_gather<<<(MP * 32 + 255) / 256, 256>>>(x, N);

    dim3 grid(MP / 128, 4);
    k_gemm_mma<<<grid, 256, SM_HALFS * 2>>>(b1, b2, out, N);
}